// round 8
// baseline (speedup 1.0000x reference)
#include <cuda_runtime.h>
#include <cuda_bf16.h>
#include <cstdint>
#include <cstddef>

#define BB 32
#define TT 512
#define II 512
#define HH 512
#define EE 4
#define GG 2048
#define KKD 1024
#define OUTD 512
#define NED 8
#define NBLK 128
#define NOUT (BB*TT*OUTD)

// ---------------- device scratch ----------------
__device__ float d_rin[BB*II];
__device__ float d_rh [BB*II];
__device__ int   d_ne[EE];
__device__ int   d_rows[EE][BB];
__device__ int   d_selE[BB][2];
__device__ int   d_selSlot[BB][2];
__device__ float d_selW[BB][2];
__device__ float d_lb_dummy[1];

__device__ float d_Whhp[(size_t)NED*16*512*128];     // 32 MB  [ed][jblk][k<512][c<128]
__device__ float d_Wihp[(size_t)EE*512*4096];        // 32 MB  [e][k<512][gp<4096]
__device__ float d_bcat[NED*16*128];
__device__ float d_xp[(size_t)EE*32*TT*4096];        // [e][slot<32][t][gp]
__device__ float d_hstate[2*(size_t)NED*BB*HH];      // parity double-buffer
__device__ float d_hout[(size_t)NED*BB*TT*HH];       // slotted outputs
__device__ float d_comb[(size_t)BB*TT*2*HH];
__device__ unsigned d_sync[NED*32];

__device__ __forceinline__ float fsig(float x)  { return 1.f/(1.f+__expf(-x)); }
__device__ __forceinline__ float ftanh(float x) { float e=__expf(2.f*x); return 1.f - 2.f/(e+1.f); }

__device__ __forceinline__ void ffma2(unsigned long long &d, unsigned long long a, unsigned long long b) {
    asm("fma.rn.f32x2 %0, %1, %2, %0;" : "+l"(d) : "l"(a), "l"(b));
}

// ---------------- prep ----------------
__global__ void k_zero() { d_sync[threadIdx.x] = 0u; }

// Whhp[ed][jblk][k][c], c=q*32+jj -> gate g = q*512 + jblk*32 + jj
__global__ void k_whhp(const float* __restrict__ Whh) {
    int idx = blockIdx.x*256 + threadIdx.x;     // 8,388,608
    int c    = idx & 127;
    int k    = (idx >> 7)  & 511;
    int jblk = (idx >> 16) & 15;
    int ed   = idx >> 20;
    int g = (c >> 5)*512 + jblk*32 + (c & 31);
    d_Whhp[idx] = __ldg(&Whh[((size_t)(ed*GG + g))*512 + k]);
}

// Wihp[e][k][gp], gp = d*2048 + jblk*128 + q*32 + jj  -> g = q*512 + jblk*32 + jj
__global__ void k_wihp(const float* __restrict__ Wih) {
    int idx = blockIdx.x*256 + threadIdx.x;     // 8,388,608
    int gp = idx & 4095;
    int k  = (idx >> 12) & 511;
    int e  = idx >> 21;
    int d    = gp >> 11;
    int rem  = gp & 2047;
    int jblk = rem >> 7;
    int c    = rem & 127;
    int g = (c >> 5)*512 + jblk*32 + (c & 31);
    d_Wihp[idx] = __ldg(&Wih[((size_t)((e*2 + d)*GG + g))*512 + k]);
}

__global__ void k_bcat(const float* __restrict__ bih, const float* __restrict__ bhh) {
    int idx = blockIdx.x*256 + threadIdx.x;     // 16384
    int c    = idx & 127;
    int jblk = (idx >> 7) & 15;
    int ed   = idx >> 11;
    int g = (c >> 5)*512 + jblk*32 + (c & 31);
    d_bcat[idx] = bih[ed*GG + g] + bhh[ed*GG + g];
}

// ---------------- router ----------------
__global__ void k_mean(const float* __restrict__ x) {
    int b = blockIdx.x, i = threadIdx.x;
    const float* p = x + (size_t)b*TT*II + i;
    float s = 0.f;
    for (int t = 0; t < TT; ++t) s += p[(size_t)t*II];
    d_rin[b*II + i] = s * (1.f/(float)TT);
}

__global__ void k_rh(const float* __restrict__ rW1, const float* __restrict__ rb1) {
    __shared__ float sr[II];
    int b = blockIdx.x, i = threadIdx.x;
    sr[i] = d_rin[b*II + i];
    __syncthreads();
    float s = rb1[i];
    const float* w = rW1 + (size_t)i*II;
    for (int k = 0; k < II; ++k) s += sr[k]*__ldg(&w[k]);
    d_rh[b*II + i] = s / (1.f + expf(-s));
}

__global__ void k_router2(const float* __restrict__ rW2, const float* __restrict__ rb2,
                          float* __restrict__ lb_out) {
    __shared__ float sl[BB][EE];
    __shared__ float sp[BB][EE];
    int tid = threadIdx.x;
    if (tid < BB*EE) {
        int b = tid >> 2, e = tid & 3;
        float s = rb2[e];
        const float* h = d_rh + b*II;
        const float* w = rW2 + e*II;
        for (int k = 0; k < II; ++k) s += h[k]*__ldg(&w[k]);
        sl[b][e] = s;
    }
    __syncthreads();
    if (tid < BB) {
        int b = tid;
        float m = sl[b][0];
        for (int e = 1; e < EE; ++e) m = fmaxf(m, sl[b][e]);
        float p[EE], sum = 0.f;
        for (int e = 0; e < EE; ++e) { p[e] = expf(sl[b][e]-m); sum += p[e]; }
        for (int e = 0; e < EE; ++e) { p[e] /= sum; sp[b][e] = p[e]; }
        int e0 = 0;
        for (int e = 1; e < EE; ++e) if (p[e] > p[e0]) e0 = e;
        int e1 = -1;
        for (int e = 0; e < EE; ++e) { if (e == e0) continue; if (e1 < 0 || p[e] > p[e1]) e1 = e; }
        float z = p[e0] + p[e1];
        d_selE[b][0] = e0; d_selE[b][1] = e1;
        d_selW[b][0] = p[e0]/z; d_selW[b][1] = p[e1]/z;
    }
    __syncthreads();
    if (tid == 0) {
        for (int e = 0; e < EE; ++e) {
            int nn = 0;
            for (int b = 0; b < BB; ++b)
                for (int k = 0; k < 2; ++k)
                    if (d_selE[b][k] == e) { d_rows[e][nn] = b; d_selSlot[b][k] = nn; nn++; }
            d_ne[e] = nn;
            for (int r = nn; r < BB; ++r) d_rows[e][r] = 0;
        }
        float lb = 0.f;
        for (int e = 0; e < EE; ++e) {
            float u = 0.f;
            for (int b = 0; b < BB; ++b) u += sp[b][e];
            u *= (1.f/(float)BB);
            float dv = u - 1.f/(float)EE;
            lb += dv*dv;
        }
        *lb_out = 0.01f * lb * (1.f/(float)EE);
    }
}

// ---------------- xp GEMM (unchanged, proven in R5) ----------------
__global__ void __launch_bounds__(256,2) k_xp(const float* __restrict__ x) {
    __shared__ float As2[8*256];
    __shared__ float Bs [8*128];
    const int e  = blockIdx.z;
    const int r  = blockIdx.y >> 2;
    if (r >= d_ne[e]) return;
    const int t0 = (blockIdx.y & 3)*128;
    const int n0 = blockIdx.x*128;
    const int tid = threadIdx.x;
    const int b = d_rows[e][r];

    const float* Arow = x + ((size_t)b*TT + t0)*II;
    const float* Bmat = d_Wihp + (size_t)e*512*4096 + n0;

    const int i0 = (tid >> 4)*8;
    const int j0 = (tid & 15)*8;

    unsigned long long acc2[8][4];
    #pragma unroll
    for (int i = 0; i < 8; ++i)
        #pragma unroll
        for (int j = 0; j < 4; ++j) acc2[i][j] = 0ull;

    const int sm = tid >> 1, skq = tid & 1;
    const int bk = tid >> 5, bn = (tid & 31)*4;

    for (int kc = 0; kc < 512; kc += 8) {
        {
            float4 v = *(const float4*)&Arow[(size_t)sm*II + kc + skq*4];
            float* dst = &As2[(skq*4)*256 + 2*sm];
            *(float2*)(dst        ) = make_float2(v.x, v.x);
            *(float2*)(dst + 256  ) = make_float2(v.y, v.y);
            *(float2*)(dst + 512  ) = make_float2(v.z, v.z);
            *(float2*)(dst + 768  ) = make_float2(v.w, v.w);
        }
        {
            float4 v = __ldg((const float4*)&Bmat[(size_t)(kc + bk)*4096 + bn]);
            *(float4*)&Bs[bk*128 + bn] = v;
        }
        __syncthreads();
        #pragma unroll
        for (int k = 0; k < 8; ++k) {
            ulonglong2 a01 = *(const ulonglong2*)&As2[k*256 + i0*2];
            ulonglong2 a23 = *(const ulonglong2*)&As2[k*256 + i0*2 + 4];
            ulonglong2 a45 = *(const ulonglong2*)&As2[k*256 + i0*2 + 8];
            ulonglong2 a67 = *(const ulonglong2*)&As2[k*256 + i0*2 + 12];
            ulonglong2 b01 = *(const ulonglong2*)&Bs[k*128 + j0];
            ulonglong2 b23 = *(const ulonglong2*)&Bs[k*128 + j0 + 4];
            ffma2(acc2[0][0], a01.x, b01.x); ffma2(acc2[0][1], a01.x, b01.y);
            ffma2(acc2[0][2], a01.x, b23.x); ffma2(acc2[0][3], a01.x, b23.y);
            ffma2(acc2[1][0], a01.y, b01.x); ffma2(acc2[1][1], a01.y, b01.y);
            ffma2(acc2[1][2], a01.y, b23.x); ffma2(acc2[1][3], a01.y, b23.y);
            ffma2(acc2[2][0], a23.x, b01.x); ffma2(acc2[2][1], a23.x, b01.y);
            ffma2(acc2[2][2], a23.x, b23.x); ffma2(acc2[2][3], a23.x, b23.y);
            ffma2(acc2[3][0], a23.y, b01.x); ffma2(acc2[3][1], a23.y, b01.y);
            ffma2(acc2[3][2], a23.y, b23.x); ffma2(acc2[3][3], a23.y, b23.y);
            ffma2(acc2[4][0], a45.x, b01.x); ffma2(acc2[4][1], a45.x, b01.y);
            ffma2(acc2[4][2], a45.x, b23.x); ffma2(acc2[4][3], a45.x, b23.y);
            ffma2(acc2[5][0], a45.y, b01.x); ffma2(acc2[5][1], a45.y, b01.y);
            ffma2(acc2[5][2], a45.y, b23.x); ffma2(acc2[5][3], a45.y, b23.y);
            ffma2(acc2[6][0], a67.x, b01.x); ffma2(acc2[6][1], a67.x, b01.y);
            ffma2(acc2[6][2], a67.x, b23.x); ffma2(acc2[6][3], a67.x, b23.y);
            ffma2(acc2[7][0], a67.y, b01.x); ffma2(acc2[7][1], a67.y, b01.y);
            ffma2(acc2[7][2], a67.y, b23.x); ffma2(acc2[7][3], a67.y, b23.y);
        }
        __syncthreads();
    }

    float* xpd = d_xp + (((size_t)e*32 + r)*TT)*4096 + n0 + j0;
    #pragma unroll
    for (int i = 0; i < 8; ++i) {
        float2 p0 = *(float2*)&acc2[i][0];
        float2 p1 = *(float2*)&acc2[i][1];
        float2 p2 = *(float2*)&acc2[i][2];
        float2 p3 = *(float2*)&acc2[i][3];
        float* dst = xpd + (size_t)(t0 + i0 + i)*4096;
        *(float4*)(dst    ) = make_float4(p0.x, p0.y, p1.x, p1.y);
        *(float4*)(dst + 4) = make_float4(p2.x, p2.y, p3.x, p3.y);
    }
}

// ---------------- persistent recurrent kernel: scalar FMA, 8 compute warps, triple buffer ----------------
// smem floats: As[16*512]=8192 | wst[3][4096]=12288 | gs[16*132]=2112
#define SMEM_RECUR ((8192 + 12288 + 2112)*4)

__global__ void __launch_bounds__(256,1) k_recur() {
    extern __shared__ float sm[];
    float* As  = sm;             // 8192
    float* wst = sm + 8192;      // 12288
    float* gs  = sm + 20480;     // 2112
    __shared__ int sN;

    const int tid  = threadIdx.x;
    const int bx   = blockIdx.x;
    const int ed   = bx >> 4;
    const int jblk = bx & 15;
    const int e    = ed >> 1;
    const int dback= ed & 1;

    const int tc = tid & 31;
    const int tr = tid >> 5;           // 0..7
    const int rg = tr & 3, ch = tr >> 2;
    const int r0 = rg*4;
    const int c0 = ch*64 + tc*2;       // column pair for this thread
    const int j0 = jblk*32;

    if (tid == 0) sN = d_ne[e];
    __syncthreads();
    const int n = sN;
    if (n == 0) return;
    const int npass = (n + 15) >> 4;

    const float2 biasv = *(const float2*)&d_bcat[(ed*16 + jblk)*128 + c0];
    const float* Wblk = d_Whhp + (size_t)(ed*16 + jblk)*65536;
    const float* xpB  = d_xp + (size_t)e*32*TT*4096 + (size_t)dback*2048 + (size_t)jblk*128 + c0;

    const int cr = tid >> 4;           // 0..15 cell row
    const int cj = (tid & 15)*2;       // 0..30 cell col pair
    float creg[2][2] = {{0.f,0.f},{0.f,0.f}};

    unsigned target = 0;
    for (int s = 0; s < TT; ++s) {
        const int t = dback ? (TT-1-s) : s;

        for (int pass = 0; pass < npass; ++pass) {
            const int prows = min(16, n - pass*16);
            const bool rowAct = (r0 < prows);

            // xp prefetch for acc init (each thread its own column pair)
            float2 xv[4];
            {
                const float* xb = xpB + ((size_t)(pass*16 + r0)*TT + t)*4096;
                xv[0] = __ldcg((const float2*)(xb));
                xv[1] = __ldcg((const float2*)(xb + (size_t)TT*4096));
                xv[2] = __ldcg((const float2*)(xb + (size_t)2*TT*4096));
                xv[3] = __ldcg((const float2*)(xb + (size_t)3*TT*4096));
            }

            // ---- stage A = h_prev (zeros for s==0 / inactive rows) ----
            if (s == 0) {
                for (int idx = tid; idx < 2048; idx += 256)
                    ((float4*)As)[idx] = make_float4(0.f,0.f,0.f,0.f);
            } else {
                const float4* hsrc = (const float4*)(d_hstate + (size_t)((s&1)^1)*(NED*BB*HH)
                                                     + (size_t)ed*(BB*HH) + (size_t)pass*16*HH);
                for (int idx = tid; idx < 2048; idx += 256) {
                    int r = idx >> 7;
                    float4 v = (r < prows) ? __ldcg(hsrc + idx) : make_float4(0.f,0.f,0.f,0.f);
                    ((float4*)As)[idx] = v;
                }
            }

            // ---- stage W chunk0 -> buf0, prefetch chunk1 ----
            float4 pf[4];
            {
                const float4* src = (const float4*)Wblk;
                float4* dst = (float4*)wst;
                #pragma unroll
                for (int i = 0; i < 4; ++i) dst[tid + i*256] = __ldcg(src + tid + i*256);
                const float4* src1 = (const float4*)(Wblk + 4096);
                #pragma unroll
                for (int i = 0; i < 4; ++i) pf[i] = __ldcg(src1 + tid + i*256);
            }
            __syncthreads();

            // ---- init accumulators ----
            float acc[4][2];
            #pragma unroll
            for (int i = 0; i < 4; ++i) {
                acc[i][0] = biasv.x + xv[i].x;
                acc[i][1] = biasv.y + xv[i].y;
            }

            // ---- 16 chunks x 32 k, triple buffer, 1 sync/chunk ----
            #pragma unroll 1
            for (int cc = 0; cc < 16; ++cc) {
                if (cc < 15) {
                    float4* dst = (float4*)(wst + ((cc+1)%3)*4096);
                    #pragma unroll
                    for (int i = 0; i < 4; ++i) dst[tid + i*256] = pf[i];
                }
                if (cc < 14) {
                    const float4* src = (const float4*)(Wblk + (size_t)(cc+2)*4096);
                    #pragma unroll
                    for (int i = 0; i < 4; ++i) pf[i] = __ldcg(src + tid + i*256);
                }
                if (rowAct) {
                    const float* wb = wst + (cc%3)*4096;
                    const int kb = cc*32;
                    #pragma unroll
                    for (int kk = 0; kk < 32; kk += 4) {
                        float4 a0 = *(const float4*)&As[(r0+0)*512 + kb + kk];
                        float4 a1 = *(const float4*)&As[(r0+1)*512 + kb + kk];
                        float4 a2 = *(const float4*)&As[(r0+2)*512 + kb + kk];
                        float4 a3 = *(const float4*)&As[(r0+3)*512 + kb + kk];
                        #pragma unroll
                        for (int u = 0; u < 4; ++u) {
                            float2 w = *(const float2*)&wb[(kk+u)*128 + c0];
                            float av0 = (&a0.x)[u], av1 = (&a1.x)[u], av2 = (&a2.x)[u], av3 = (&a3.x)[u];
                            acc[0][0] += av0*w.x; acc[0][1] += av0*w.y;
                            acc[1][0] += av1*w.x; acc[1][1] += av1*w.y;
                            acc[2][0] += av2*w.x; acc[2][1] += av2*w.y;
                            acc[3][0] += av3*w.x; acc[3][1] += av3*w.y;
                        }
                    }
                }
                __syncthreads();
            }

            // ---- gates to smem ----
            if (rowAct) {
                #pragma unroll
                for (int i = 0; i < 4; ++i)
                    *(float2*)&gs[(r0+i)*132 + c0] = make_float2(acc[i][0], acc[i][1]);
            }
            __syncthreads();

            // ---- LSTM cell update ----
            if (cr < prows) {
                float hv[2];
                #pragma unroll
                for (int v2 = 0; v2 < 2; ++v2) {
                    int jj = cj + v2;
                    float ig = fsig (gs[cr*132 +      jj]);
                    float fg = fsig (gs[cr*132 + 32 + jj]);
                    float gg = ftanh(gs[cr*132 + 64 + jj]);
                    float og = fsig (gs[cr*132 + 96 + jj]);
                    float c = fg*creg[pass][v2] + ig*gg;
                    creg[pass][v2] = c;
                    hv[v2] = og * ftanh(c);
                }
                float2 h2 = make_float2(hv[0], hv[1]);
                __stcg((float2*)&d_hstate[(size_t)(s&1)*(NED*BB*HH) + (size_t)ed*(BB*HH)
                                          + (pass*16+cr)*HH + j0 + cj], h2);
                __stcg((float2*)&d_hout[(((size_t)(ed*BB + pass*16 + cr))*TT + t)*HH + j0 + cj], h2);
            }
            __syncthreads();
        } // pass

        // ---- per-(e,d) grid barrier ----
        __threadfence();
        __syncthreads();
        target += 16;
        if (tid == 0) {
            asm volatile("red.release.gpu.global.add.u32 [%0], %1;" :: "l"(d_sync + ed*32), "r"(1u) : "memory");
            unsigned v;
            do {
                asm volatile("ld.acquire.gpu.global.u32 %0, [%1];" : "=r"(v) : "l"(d_sync + ed*32) : "memory");
            } while (v < target);
        }
        __syncthreads();
    }
}

// ---------------- combine ----------------
__global__ void k_combine() {
    int idx = blockIdx.x*256 + threadIdx.x;
    int dj4 = idx & 255;
    int t   = (idx >> 8) & 511;
    int b   = idx >> 17;
    int d   = dj4 >> 7;
    int j4  = dj4 & 127;
    float w0 = d_selW[b][0], w1 = d_selW[b][1];
    int e0 = d_selE[b][0],   e1 = d_selE[b][1];
    int s0 = d_selSlot[b][0], s1 = d_selSlot[b][1];
    float4 h0 = *(const float4*)&d_hout[(((size_t)((e0*2+d)*BB + s0))*TT + t)*HH + j4*4];
    float4 h1 = *(const float4*)&d_hout[(((size_t)((e1*2+d)*BB + s1))*TT + t)*HH + j4*4];
    float4 r;
    r.x = w0*h0.x + w1*h1.x; r.y = w0*h0.y + w1*h1.y;
    r.z = w0*h0.z + w1*h1.z; r.w = w0*h0.w + w1*h1.w;
    ((float4*)d_comb)[idx] = r;
}

// ---------------- out GEMM ----------------
__global__ void __launch_bounds__(256) k_outgemm(float* __restrict__ out,
                                                 const float* __restrict__ Wout,
                                                 const float* __restrict__ bout) {
    __shared__ float As[16][68];
    __shared__ float Bs[16][68];
    const int tid = threadIdx.x;
    const int m0 = blockIdx.y*64;
    const int n0 = blockIdx.x*64;
    const int tm = tid >> 4, tn = tid & 15;
    float acc[4][4] = {};
    const int r = tid >> 2, q = tid & 3;
    for (int kc = 0; kc < KKD; kc += 16) {
        float4 a = *(const float4*)&d_comb[(size_t)(m0+r)*KKD + kc + q*4];
        As[q*4+0][r]=a.x; As[q*4+1][r]=a.y; As[q*4+2][r]=a.z; As[q*4+3][r]=a.w;
        float4 bb = __ldg((const float4*)&Wout[(size_t)(n0+r)*KKD + kc + q*4]);
        Bs[q*4+0][r]=bb.x; Bs[q*4+1][r]=bb.y; Bs[q*4+2][r]=bb.z; Bs[q*4+3][r]=bb.w;
        __syncthreads();
        #pragma unroll
        for (int k = 0; k < 16; ++k) {
            float4 av = *(const float4*)&As[k][tm*4];
            float4 bv = *(const float4*)&Bs[k][tn*4];
            acc[0][0]+=av.x*bv.x; acc[0][1]+=av.x*bv.y; acc[0][2]+=av.x*bv.z; acc[0][3]+=av.x*bv.w;
            acc[1][0]+=av.y*bv.x; acc[1][1]+=av.y*bv.y; acc[1][2]+=av.y*bv.z; acc[1][3]+=av.y*bv.w;
            acc[2][0]+=av.z*bv.x; acc[2][1]+=av.z*bv.y; acc[2][2]+=av.z*bv.z; acc[2][3]+=av.z*bv.w;
            acc[3][0]+=av.w*bv.x; acc[3][1]+=av.w*bv.y; acc[3][2]+=av.w*bv.z; acc[3][3]+=av.w*bv.w;
        }
        __syncthreads();
    }
    float4 bv = *(const float4*)&bout[n0 + tn*4];
    #pragma unroll
    for (int i = 0; i < 4; ++i) {
        float4 o;
        o.x = acc[i][0]+bv.x; o.y = acc[i][1]+bv.y; o.z = acc[i][2]+bv.z; o.w = acc[i][3]+bv.w;
        *(float4*)&out[(size_t)(m0+tm*4+i)*OUTD + n0 + tn*4] = o;
    }
}

// ---------------- launch ----------------
extern "C" void kernel_launch(void* const* d_in, const int* in_sizes, int n_in,
                              void* d_out, int out_size) {
    const float* x    = (const float*)d_in[0];
    const float* rW1  = (const float*)d_in[1];
    const float* rb1  = (const float*)d_in[2];
    const float* rW2  = (const float*)d_in[3];
    const float* rb2  = (const float*)d_in[4];
    const float* Wih  = (const float*)d_in[5];
    const float* Whh  = (const float*)d_in[6];
    const float* bih  = (const float*)d_in[7];
    const float* bhh  = (const float*)d_in[8];
    const float* Wout = (const float*)d_in[9];
    const float* bout = (const float*)d_in[10];
    float* out = (float*)d_out;

    float* lbdst;
    if (out_size > NOUT) {
        lbdst = out + NOUT;
    } else {
        cudaGetSymbolAddress((void**)&lbdst, d_lb_dummy);
    }

    static bool attrDone = false;
    if (!attrDone) {
        cudaFuncSetAttribute(k_recur, cudaFuncAttributeMaxDynamicSharedMemorySize, SMEM_RECUR);
        attrDone = true;
    }

    k_zero<<<1, NED*32>>>();
    k_whhp<<<32768, 256>>>(Whh);
    k_wihp<<<32768, 256>>>(Wih);
    k_bcat<<<64, 256>>>(bih, bhh);
    k_mean<<<BB, II>>>(x);
    k_rh<<<BB, II>>>(rW1, rb1);
    k_router2<<<1, 128>>>(rW2, rb2, lbdst);
    k_xp<<<dim3(32, 128, EE), 256>>>(x);
    k_recur<<<NBLK, 256, SMEM_RECUR>>>();
    k_combine<<<16384, 256>>>();
    dim3 g(OUTD/64, (BB*TT)/64);
    k_outgemm<<<g, 256>>>(out, Wout, bout);
}

// round 9
// speedup vs baseline: 1.2641x; 1.2641x over previous
#include <cuda_runtime.h>
#include <cuda_bf16.h>
#include <cstdint>
#include <cstddef>

#define BB 32
#define TT 512
#define II 512
#define HH 512
#define EE 4
#define GG 2048
#define KKD 1024
#define OUTD 512
#define NED 8
#define NBLK 128
#define NOUT (BB*TT*OUTD)

// ---------------- device scratch ----------------
__device__ float d_rin[BB*II];
__device__ float d_rh [BB*II];
__device__ int   d_ne[EE];
__device__ int   d_rows[EE][BB];
__device__ int   d_selE[BB][2];
__device__ int   d_selSlot[BB][2];
__device__ float d_selW[BB][2];
__device__ float d_lb_dummy[1];

__device__ float d_Whhp[(size_t)NED*16*512*128];     // 32 MB  [ed][jblk][k<512][c<128]
__device__ float d_Wihp[(size_t)EE*512*4096];        // 32 MB  [e][k<512][gp<4096]
__device__ float d_bcat[NED*16*128];
__device__ float d_xp[(size_t)EE*32*TT*4096];        // [e][slot<32][t][gp]
__device__ float d_hstate[2*(size_t)NED*BB*HH];      // parity double-buffer
__device__ float d_hout[(size_t)NED*BB*TT*HH];       // slotted outputs
__device__ float d_comb[(size_t)BB*TT*2*HH];
__device__ unsigned d_sync[NED*32];

__device__ __forceinline__ float fsig(float x)  { return 1.f/(1.f+__expf(-x)); }
__device__ __forceinline__ float ftanh(float x) { float e=__expf(2.f*x); return 1.f - 2.f/(e+1.f); }

__device__ __forceinline__ void ffma2(unsigned long long &d, unsigned long long a, unsigned long long b) {
    asm("fma.rn.f32x2 %0, %1, %2, %0;" : "+l"(d) : "l"(a), "l"(b));
}

// ---------------- prep ----------------
__global__ void k_zero() { d_sync[threadIdx.x] = 0u; }

// Whhp[ed][jblk][k][c], c=q*32+jj -> gate g = q*512 + jblk*32 + jj
__global__ void k_whhp(const float* __restrict__ Whh) {
    int idx = blockIdx.x*256 + threadIdx.x;     // 8,388,608
    int c    = idx & 127;
    int k    = (idx >> 7)  & 511;
    int jblk = (idx >> 16) & 15;
    int ed   = idx >> 20;
    int g = (c >> 5)*512 + jblk*32 + (c & 31);
    d_Whhp[idx] = __ldg(&Whh[((size_t)(ed*GG + g))*512 + k]);
}

// Wihp[e][k][gp], gp = d*2048 + jblk*128 + q*32 + jj  -> g = q*512 + jblk*32 + jj
__global__ void k_wihp(const float* __restrict__ Wih) {
    int idx = blockIdx.x*256 + threadIdx.x;     // 8,388,608
    int gp = idx & 4095;
    int k  = (idx >> 12) & 511;
    int e  = idx >> 21;
    int d    = gp >> 11;
    int rem  = gp & 2047;
    int jblk = rem >> 7;
    int c    = rem & 127;
    int g = (c >> 5)*512 + jblk*32 + (c & 31);
    d_Wihp[idx] = __ldg(&Wih[((size_t)((e*2 + d)*GG + g))*512 + k]);
}

__global__ void k_bcat(const float* __restrict__ bih, const float* __restrict__ bhh) {
    int idx = blockIdx.x*256 + threadIdx.x;     // 16384
    int c    = idx & 127;
    int jblk = (idx >> 7) & 15;
    int ed   = idx >> 11;
    int g = (c >> 5)*512 + jblk*32 + (c & 31);
    d_bcat[idx] = bih[ed*GG + g] + bhh[ed*GG + g];
}

// ---------------- router ----------------
__global__ void k_mean(const float* __restrict__ x) {
    int b = blockIdx.x, i = threadIdx.x;
    const float* p = x + (size_t)b*TT*II + i;
    float s = 0.f;
    for (int t = 0; t < TT; ++t) s += p[(size_t)t*II];
    d_rin[b*II + i] = s * (1.f/(float)TT);
}

__global__ void k_rh(const float* __restrict__ rW1, const float* __restrict__ rb1) {
    __shared__ float sr[II];
    int b = blockIdx.x, i = threadIdx.x;
    sr[i] = d_rin[b*II + i];
    __syncthreads();
    float s = rb1[i];
    const float* w = rW1 + (size_t)i*II;
    for (int k = 0; k < II; ++k) s += sr[k]*__ldg(&w[k]);
    d_rh[b*II + i] = s / (1.f + expf(-s));
}

__global__ void k_router2(const float* __restrict__ rW2, const float* __restrict__ rb2,
                          float* __restrict__ lb_out) {
    __shared__ float sl[BB][EE];
    __shared__ float sp[BB][EE];
    int tid = threadIdx.x;
    if (tid < BB*EE) {
        int b = tid >> 2, e = tid & 3;
        float s = rb2[e];
        const float* h = d_rh + b*II;
        const float* w = rW2 + e*II;
        for (int k = 0; k < II; ++k) s += h[k]*__ldg(&w[k]);
        sl[b][e] = s;
    }
    __syncthreads();
    if (tid < BB) {
        int b = tid;
        float m = sl[b][0];
        for (int e = 1; e < EE; ++e) m = fmaxf(m, sl[b][e]);
        float p[EE], sum = 0.f;
        for (int e = 0; e < EE; ++e) { p[e] = expf(sl[b][e]-m); sum += p[e]; }
        for (int e = 0; e < EE; ++e) { p[e] /= sum; sp[b][e] = p[e]; }
        int e0 = 0;
        for (int e = 1; e < EE; ++e) if (p[e] > p[e0]) e0 = e;
        int e1 = -1;
        for (int e = 0; e < EE; ++e) { if (e == e0) continue; if (e1 < 0 || p[e] > p[e1]) e1 = e; }
        float z = p[e0] + p[e1];
        d_selE[b][0] = e0; d_selE[b][1] = e1;
        d_selW[b][0] = p[e0]/z; d_selW[b][1] = p[e1]/z;
    }
    __syncthreads();
    if (tid == 0) {
        for (int e = 0; e < EE; ++e) {
            int nn = 0;
            for (int b = 0; b < BB; ++b)
                for (int k = 0; k < 2; ++k)
                    if (d_selE[b][k] == e) { d_rows[e][nn] = b; d_selSlot[b][k] = nn; nn++; }
            d_ne[e] = nn;
            for (int r = nn; r < BB; ++r) d_rows[e][r] = 0;
        }
        float lb = 0.f;
        for (int e = 0; e < EE; ++e) {
            float u = 0.f;
            for (int b = 0; b < BB; ++b) u += sp[b][e];
            u *= (1.f/(float)BB);
            float dv = u - 1.f/(float)EE;
            lb += dv*dv;
        }
        *lb_out = 0.01f * lb * (1.f/(float)EE);
    }
}

// ---------------- xp GEMM (unchanged, proven in R5) ----------------
__global__ void __launch_bounds__(256,2) k_xp(const float* __restrict__ x) {
    __shared__ float As2[8*256];
    __shared__ float Bs [8*128];
    const int e  = blockIdx.z;
    const int r  = blockIdx.y >> 2;
    if (r >= d_ne[e]) return;
    const int t0 = (blockIdx.y & 3)*128;
    const int n0 = blockIdx.x*128;
    const int tid = threadIdx.x;
    const int b = d_rows[e][r];

    const float* Arow = x + ((size_t)b*TT + t0)*II;
    const float* Bmat = d_Wihp + (size_t)e*512*4096 + n0;

    const int i0 = (tid >> 4)*8;
    const int j0 = (tid & 15)*8;

    unsigned long long acc2[8][4];
    #pragma unroll
    for (int i = 0; i < 8; ++i)
        #pragma unroll
        for (int j = 0; j < 4; ++j) acc2[i][j] = 0ull;

    const int sm = tid >> 1, skq = tid & 1;
    const int bk = tid >> 5, bn = (tid & 31)*4;

    for (int kc = 0; kc < 512; kc += 8) {
        {
            float4 v = *(const float4*)&Arow[(size_t)sm*II + kc + skq*4];
            float* dst = &As2[(skq*4)*256 + 2*sm];
            *(float2*)(dst        ) = make_float2(v.x, v.x);
            *(float2*)(dst + 256  ) = make_float2(v.y, v.y);
            *(float2*)(dst + 512  ) = make_float2(v.z, v.z);
            *(float2*)(dst + 768  ) = make_float2(v.w, v.w);
        }
        {
            float4 v = __ldg((const float4*)&Bmat[(size_t)(kc + bk)*4096 + bn]);
            *(float4*)&Bs[bk*128 + bn] = v;
        }
        __syncthreads();
        #pragma unroll
        for (int k = 0; k < 8; ++k) {
            ulonglong2 a01 = *(const ulonglong2*)&As2[k*256 + i0*2];
            ulonglong2 a23 = *(const ulonglong2*)&As2[k*256 + i0*2 + 4];
            ulonglong2 a45 = *(const ulonglong2*)&As2[k*256 + i0*2 + 8];
            ulonglong2 a67 = *(const ulonglong2*)&As2[k*256 + i0*2 + 12];
            ulonglong2 b01 = *(const ulonglong2*)&Bs[k*128 + j0];
            ulonglong2 b23 = *(const ulonglong2*)&Bs[k*128 + j0 + 4];
            ffma2(acc2[0][0], a01.x, b01.x); ffma2(acc2[0][1], a01.x, b01.y);
            ffma2(acc2[0][2], a01.x, b23.x); ffma2(acc2[0][3], a01.x, b23.y);
            ffma2(acc2[1][0], a01.y, b01.x); ffma2(acc2[1][1], a01.y, b01.y);
            ffma2(acc2[1][2], a01.y, b23.x); ffma2(acc2[1][3], a01.y, b23.y);
            ffma2(acc2[2][0], a23.x, b01.x); ffma2(acc2[2][1], a23.x, b01.y);
            ffma2(acc2[2][2], a23.x, b23.x); ffma2(acc2[2][3], a23.x, b23.y);
            ffma2(acc2[3][0], a23.y, b01.x); ffma2(acc2[3][1], a23.y, b01.y);
            ffma2(acc2[3][2], a23.y, b23.x); ffma2(acc2[3][3], a23.y, b23.y);
            ffma2(acc2[4][0], a45.x, b01.x); ffma2(acc2[4][1], a45.x, b01.y);
            ffma2(acc2[4][2], a45.x, b23.x); ffma2(acc2[4][3], a45.x, b23.y);
            ffma2(acc2[5][0], a45.y, b01.x); ffma2(acc2[5][1], a45.y, b01.y);
            ffma2(acc2[5][2], a45.y, b23.x); ffma2(acc2[5][3], a45.y, b23.y);
            ffma2(acc2[6][0], a67.x, b01.x); ffma2(acc2[6][1], a67.x, b01.y);
            ffma2(acc2[6][2], a67.x, b23.x); ffma2(acc2[6][3], a67.x, b23.y);
            ffma2(acc2[7][0], a67.y, b01.x); ffma2(acc2[7][1], a67.y, b01.y);
            ffma2(acc2[7][2], a67.y, b23.x); ffma2(acc2[7][3], a67.y, b23.y);
        }
        __syncthreads();
    }

    float* xpd = d_xp + (((size_t)e*32 + r)*TT)*4096 + n0 + j0;
    #pragma unroll
    for (int i = 0; i < 8; ++i) {
        float2 p0 = *(float2*)&acc2[i][0];
        float2 p1 = *(float2*)&acc2[i][1];
        float2 p2 = *(float2*)&acc2[i][2];
        float2 p3 = *(float2*)&acc2[i][3];
        float* dst = xpd + (size_t)(t0 + i0 + i)*4096;
        *(float4*)(dst    ) = make_float4(p0.x, p0.y, p1.x, p1.y);
        *(float4*)(dst + 4) = make_float4(p2.x, p2.y, p3.x, p3.y);
    }
}

// ---------------- recur compute body: RW interleaved rows (tr, tr+8, ...) ----------------
template<int RW>
__device__ __forceinline__ void chunk_fma(const float* __restrict__ As,
                                          const float* __restrict__ wsc,
                                          int tr, int c0, float acc[4][4]) {
    #pragma unroll
    for (int kk = 0; kk < 32; kk += 4) {
        float4 a[RW];
        #pragma unroll
        for (int i = 0; i < RW; ++i)
            a[i] = *(const float4*)&As[(tr + 8*i)*512 /*row*/ + kk];
        #pragma unroll
        for (int u = 0; u < 4; ++u) {
            float4 w = *(const float4*)&wsc[(kk+u)*128 + c0];
            #pragma unroll
            for (int i = 0; i < RW; ++i) {
                float av = (&a[i].x)[u];
                acc[i][0] += av*w.x; acc[i][1] += av*w.y;
                acc[i][2] += av*w.z; acc[i][3] += av*w.w;
            }
        }
    }
}

// ---------------- persistent recurrent kernel: single pass, 32-row capacity, interleaved rows ----------------
// smem floats: As[32*512]=16384 | ws[2][4096]=8192 | gs[32*132]=4224
#define SMEM_RECUR ((16384 + 8192 + 4224)*4)
#define NCH 16

__global__ void __launch_bounds__(256,1) k_recur() {
    extern __shared__ float sm[];
    float* As = sm;                    // 16384
    float* ws = sm + 16384;            // 8192
    float* gs = sm + 24576;            // 4224
    __shared__ int sN;

    const int tid  = threadIdx.x;
    const int bx   = blockIdx.x;
    const int ed   = bx >> 4;
    const int jblk = bx & 15;
    const int e    = ed >> 1;
    const int dback= ed & 1;
    const int tc = tid & 31, tr = tid >> 5;   // tr = warp 0..7
    const int c0 = tc*4;
    const int j0 = jblk*32;

    if (tid == 0) sN = d_ne[e];
    __syncthreads();
    const int n = sN;
    if (n == 0) return;

    // warp tr owns rows tr, tr+8, tr+16, tr+24 (those < n); prefix count:
    int rw = (n - tr + 7) >> 3;
    if (rw < 0) rw = 0;
    if (rw > 4) rw = 4;

    const float4 biasv = *(const float4*)&d_bcat[(ed*16 + jblk)*128 + c0];
    const float* Wblk = d_Whhp + (size_t)(ed*16 + jblk)*65536;
    const float* xpB  = d_xp + (size_t)e*32*TT*4096 + (size_t)dback*2048 + (size_t)jblk*128 + c0;

    const int cr = tid >> 4;           // 0..15: thread owns rows cr and cr+16
    const int cj = (tid & 15)*2;       // col pair
    float creg[2][2] = {{0.f,0.f},{0.f,0.f}};

    unsigned target = 0;
    for (int s = 0; s < TT; ++s) {
        const int t = dback ? (TT-1-s) : s;

        // ---- xp prefetch for this thread's rows ----
        float4 xv[4];
        #pragma unroll
        for (int i = 0; i < 4; ++i) {
            if (i < rw)
                xv[i] = __ldcg((const float4*)(xpB + ((size_t)(tr + 8*i)*TT + t)*4096));
        }

        // ---- stage A = h_prev for rows < n ----
        if (s == 0) {
            for (int idx = tid; idx < n*128; idx += 256)
                ((float4*)As)[idx] = make_float4(0.f,0.f,0.f,0.f);
        } else {
            const float4* hsrc = (const float4*)(d_hstate + (size_t)((s&1)^1)*(NED*BB*HH)
                                                 + (size_t)ed*(BB*HH));
            for (int idx = tid; idx < n*128; idx += 256)
                ((float4*)As)[idx] = __ldcg(hsrc + idx);
        }
        // ---- stage W chunk 0 ----
        {
            const float4* src = (const float4*)Wblk;
            float4* dst = (float4*)ws;
            dst[tid]     = __ldcg(src+tid);     dst[tid+256] = __ldcg(src+tid+256);
            dst[tid+512] = __ldcg(src+tid+512); dst[tid+768] = __ldcg(src+tid+768);
        }
        __syncthreads();

        // ---- init accumulators ----
        float acc[4][4];
        #pragma unroll
        for (int i = 0; i < 4; ++i) {
            if (i < rw) {
                acc[i][0] = biasv.x + xv[i].x; acc[i][1] = biasv.y + xv[i].y;
                acc[i][2] = biasv.z + xv[i].z; acc[i][3] = biasv.w + xv[i].w;
            }
        }

        // ---- 16 chunks x 32 k, double buffer (R5-proven shape) ----
        int cur = 0;
        #pragma unroll 1
        for (int kc = 0; kc < NCH; ++kc) {
            float4 pf0, pf1, pf2, pf3;
            if (kc < NCH-1) {
                const float4* src = (const float4*)(Wblk + (size_t)(kc+1)*4096);
                pf0 = __ldcg(src+tid);     pf1 = __ldcg(src+tid+256);
                pf2 = __ldcg(src+tid+512); pf3 = __ldcg(src+tid+768);
            }
            {
                const float* wsc = ws + cur*4096;
                const float* Ak  = As + kc*32;
                switch (rw) {
                    case 4: chunk_fma<4>(Ak, wsc, tr, c0, acc); break;
                    case 3: chunk_fma<3>(Ak, wsc, tr, c0, acc); break;
                    case 2: chunk_fma<2>(Ak, wsc, tr, c0, acc); break;
                    case 1: chunk_fma<1>(Ak, wsc, tr, c0, acc); break;
                    default: break;
                }
            }
            __syncthreads();
            if (kc < NCH-1) {
                float4* dst = (float4*)(ws + (cur^1)*4096);
                dst[tid] = pf0; dst[tid+256] = pf1; dst[tid+512] = pf2; dst[tid+768] = pf3;
            }
            __syncthreads();
            cur ^= 1;
        }

        // ---- gates to smem ----
        #pragma unroll
        for (int i = 0; i < 4; ++i) {
            if (i < rw)
                *(float4*)&gs[(tr + 8*i)*132 + c0] = make_float4(acc[i][0],acc[i][1],acc[i][2],acc[i][3]);
        }
        __syncthreads();

        // ---- LSTM cell update: rows cr and cr+16 ----
        #pragma unroll
        for (int half = 0; half < 2; ++half) {
            const int row = cr + half*16;
            if (row < n) {
                float hv[2];
                #pragma unroll
                for (int v2 = 0; v2 < 2; ++v2) {
                    int jj = cj + v2;
                    float ig = fsig (gs[row*132 +      jj]);
                    float fg = fsig (gs[row*132 + 32 + jj]);
                    float gg = ftanh(gs[row*132 + 64 + jj]);
                    float og = fsig (gs[row*132 + 96 + jj]);
                    float c = fg*creg[half][v2] + ig*gg;
                    creg[half][v2] = c;
                    hv[v2] = og * ftanh(c);
                }
                float2 h2 = make_float2(hv[0], hv[1]);
                __stcg((float2*)&d_hstate[(size_t)(s&1)*(NED*BB*HH) + (size_t)ed*(BB*HH)
                                          + row*HH + j0 + cj], h2);
                __stcg((float2*)&d_hout[(((size_t)(ed*BB + row))*TT + t)*HH + j0 + cj], h2);
            }
        }
        __threadfence();
        __syncthreads();

        // ---- per-(e,d) grid barrier ----
        target += 16;
        if (tid == 0) {
            asm volatile("red.release.gpu.global.add.u32 [%0], %1;" :: "l"(d_sync + ed*32), "r"(1u) : "memory");
            unsigned v;
            do {
                asm volatile("ld.acquire.gpu.global.u32 %0, [%1];" : "=r"(v) : "l"(d_sync + ed*32) : "memory");
            } while (v < target);
        }
        __syncthreads();
    }
}

// ---------------- combine ----------------
__global__ void k_combine() {
    int idx = blockIdx.x*256 + threadIdx.x;
    int dj4 = idx & 255;
    int t   = (idx >> 8) & 511;
    int b   = idx >> 17;
    int d   = dj4 >> 7;
    int j4  = dj4 & 127;
    float w0 = d_selW[b][0], w1 = d_selW[b][1];
    int e0 = d_selE[b][0],   e1 = d_selE[b][1];
    int s0 = d_selSlot[b][0], s1 = d_selSlot[b][1];
    float4 h0 = *(const float4*)&d_hout[(((size_t)((e0*2+d)*BB + s0))*TT + t)*HH + j4*4];
    float4 h1 = *(const float4*)&d_hout[(((size_t)((e1*2+d)*BB + s1))*TT + t)*HH + j4*4];
    float4 r;
    r.x = w0*h0.x + w1*h1.x; r.y = w0*h0.y + w1*h1.y;
    r.z = w0*h0.z + w1*h1.z; r.w = w0*h0.w + w1*h1.w;
    ((float4*)d_comb)[idx] = r;
}

// ---------------- out GEMM ----------------
__global__ void __launch_bounds__(256) k_outgemm(float* __restrict__ out,
                                                 const float* __restrict__ Wout,
                                                 const float* __restrict__ bout) {
    __shared__ float As[16][68];
    __shared__ float Bs[16][68];
    const int tid = threadIdx.x;
    const int m0 = blockIdx.y*64;
    const int n0 = blockIdx.x*64;
    const int tm = tid >> 4, tn = tid & 15;
    float acc[4][4] = {};
    const int r = tid >> 2, q = tid & 3;
    for (int kc = 0; kc < KKD; kc += 16) {
        float4 a = *(const float4*)&d_comb[(size_t)(m0+r)*KKD + kc + q*4];
        As[q*4+0][r]=a.x; As[q*4+1][r]=a.y; As[q*4+2][r]=a.z; As[q*4+3][r]=a.w;
        float4 bb = __ldg((const float4*)&Wout[(size_t)(n0+r)*KKD + kc + q*4]);
        Bs[q*4+0][r]=bb.x; Bs[q*4+1][r]=bb.y; Bs[q*4+2][r]=bb.z; Bs[q*4+3][r]=bb.w;
        __syncthreads();
        #pragma unroll
        for (int k = 0; k < 16; ++k) {
            float4 av = *(const float4*)&As[k][tm*4];
            float4 bv = *(const float4*)&Bs[k][tn*4];
            acc[0][0]+=av.x*bv.x; acc[0][1]+=av.x*bv.y; acc[0][2]+=av.x*bv.z; acc[0][3]+=av.x*bv.w;
            acc[1][0]+=av.y*bv.x; acc[1][1]+=av.y*bv.y; acc[1][2]+=av.y*bv.z; acc[1][3]+=av.y*bv.w;
            acc[2][0]+=av.z*bv.x; acc[2][1]+=av.z*bv.y; acc[2][2]+=av.z*bv.z; acc[2][3]+=av.z*bv.w;
            acc[3][0]+=av.w*bv.x; acc[3][1]+=av.w*bv.y; acc[3][2]+=av.w*bv.z; acc[3][3]+=av.w*bv.w;
        }
        __syncthreads();
    }
    float4 bv = *(const float4*)&bout[n0 + tn*4];
    #pragma unroll
    for (int i = 0; i < 4; ++i) {
        float4 o;
        o.x = acc[i][0]+bv.x; o.y = acc[i][1]+bv.y; o.z = acc[i][2]+bv.z; o.w = acc[i][3]+bv.w;
        *(float4*)&out[(size_t)(m0+tm*4+i)*OUTD + n0 + tn*4] = o;
    }
}

// ---------------- launch ----------------
extern "C" void kernel_launch(void* const* d_in, const int* in_sizes, int n_in,
                              void* d_out, int out_size) {
    const float* x    = (const float*)d_in[0];
    const float* rW1  = (const float*)d_in[1];
    const float* rb1  = (const float*)d_in[2];
    const float* rW2  = (const float*)d_in[3];
    const float* rb2  = (const float*)d_in[4];
    const float* Wih  = (const float*)d_in[5];
    const float* Whh  = (const float*)d_in[6];
    const float* bih  = (const float*)d_in[7];
    const float* bhh  = (const float*)d_in[8];
    const float* Wout = (const float*)d_in[9];
    const float* bout = (const float*)d_in[10];
    float* out = (float*)d_out;

    float* lbdst;
    if (out_size > NOUT) {
        lbdst = out + NOUT;
    } else {
        cudaGetSymbolAddress((void**)&lbdst, d_lb_dummy);
    }

    static bool attrDone = false;
    if (!attrDone) {
        cudaFuncSetAttribute(k_recur, cudaFuncAttributeMaxDynamicSharedMemorySize, SMEM_RECUR);
        attrDone = true;
    }

    k_zero<<<1, NED*32>>>();
    k_whhp<<<32768, 256>>>(Whh);
    k_wihp<<<32768, 256>>>(Wih);
    k_bcat<<<64, 256>>>(bih, bhh);
    k_mean<<<BB, II>>>(x);
    k_rh<<<BB, II>>>(rW1, rb1);
    k_router2<<<1, 128>>>(rW2, rb2, lbdst);
    k_xp<<<dim3(32, 128, EE), 256>>>(x);
    k_recur<<<NBLK, 256, SMEM_RECUR>>>();
    k_combine<<<16384, 256>>>();
    dim3 g(OUTD/64, (BB*TT)/64);
    k_outgemm<<<g, 256>>>(out, Wout, bout);
}

// round 10
// speedup vs baseline: 1.2957x; 1.0250x over previous
#include <cuda_runtime.h>
#include <cuda_bf16.h>
#include <cstdint>
#include <cstddef>

#define BB 32
#define TT 512
#define II 512
#define HH 512
#define EE 4
#define GG 2048
#define KKD 1024
#define OUTD 512
#define NED 8
#define NBLK 128
#define NOUT (BB*TT*OUTD)

// ---------------- device scratch ----------------
__device__ float d_rin[BB*II];
__device__ float d_rh [BB*II];
__device__ int   d_ne[EE];
__device__ int   d_rows[EE][BB];
__device__ int   d_selE[BB][2];
__device__ int   d_selSlot[BB][2];
__device__ float d_selW[BB][2];
__device__ float d_lb_dummy[1];

__device__ float d_Whhp[(size_t)NED*16*512*128];     // 32 MB  [ed][jblk][k<512][c<128]
__device__ float d_Wihp[(size_t)EE*512*4096];        // 32 MB  [e][k<512][gp<4096]
__device__ float d_bcat[NED*16*128];
__device__ float d_xp[(size_t)EE*32*TT*4096];        // [e][slot<32][t][gp]
__device__ float d_hstate[2*(size_t)NED*BB*HH];      // parity double-buffer
__device__ float d_hout[(size_t)NED*BB*TT*HH];       // slotted outputs
__device__ float d_comb[(size_t)BB*TT*2*HH];
__device__ unsigned d_sync[NED*32];

__device__ __forceinline__ float fsig(float x)  { return 1.f/(1.f+__expf(-x)); }
__device__ __forceinline__ float ftanh(float x) { float e=__expf(2.f*x); return 1.f - 2.f/(e+1.f); }

__device__ __forceinline__ void ffma2(unsigned long long &d, unsigned long long a, unsigned long long b) {
    asm("fma.rn.f32x2 %0, %1, %2, %0;" : "+l"(d) : "l"(a), "l"(b));
}

// ---------------- prep ----------------
__global__ void k_zero() { d_sync[threadIdx.x] = 0u; }

// Whhp[ed][jblk][k][c], c=q*32+jj -> gate g = q*512 + jblk*32 + jj
__global__ void k_whhp(const float* __restrict__ Whh) {
    int idx = blockIdx.x*256 + threadIdx.x;     // 8,388,608
    int c    = idx & 127;
    int k    = (idx >> 7)  & 511;
    int jblk = (idx >> 16) & 15;
    int ed   = idx >> 20;
    int g = (c >> 5)*512 + jblk*32 + (c & 31);
    d_Whhp[idx] = __ldg(&Whh[((size_t)(ed*GG + g))*512 + k]);
}

// Wihp[e][k][gp], gp = d*2048 + jblk*128 + q*32 + jj  -> g = q*512 + jblk*32 + jj
__global__ void k_wihp(const float* __restrict__ Wih) {
    int idx = blockIdx.x*256 + threadIdx.x;     // 8,388,608
    int gp = idx & 4095;
    int k  = (idx >> 12) & 511;
    int e  = idx >> 21;
    int d    = gp >> 11;
    int rem  = gp & 2047;
    int jblk = rem >> 7;
    int c    = rem & 127;
    int g = (c >> 5)*512 + jblk*32 + (c & 31);
    d_Wihp[idx] = __ldg(&Wih[((size_t)((e*2 + d)*GG + g))*512 + k]);
}

__global__ void k_bcat(const float* __restrict__ bih, const float* __restrict__ bhh) {
    int idx = blockIdx.x*256 + threadIdx.x;     // 16384
    int c    = idx & 127;
    int jblk = (idx >> 7) & 15;
    int ed   = idx >> 11;
    int g = (c >> 5)*512 + jblk*32 + (c & 31);
    d_bcat[idx] = bih[ed*GG + g] + bhh[ed*GG + g];
}

// ---------------- router ----------------
__global__ void k_mean(const float* __restrict__ x) {
    int b = blockIdx.x, i = threadIdx.x;
    const float* p = x + (size_t)b*TT*II + i;
    float s = 0.f;
    for (int t = 0; t < TT; ++t) s += p[(size_t)t*II];
    d_rin[b*II + i] = s * (1.f/(float)TT);
}

__global__ void k_rh(const float* __restrict__ rW1, const float* __restrict__ rb1) {
    __shared__ float sr[II];
    int b = blockIdx.x, i = threadIdx.x;
    sr[i] = d_rin[b*II + i];
    __syncthreads();
    float s = rb1[i];
    const float* w = rW1 + (size_t)i*II;
    for (int k = 0; k < II; ++k) s += sr[k]*__ldg(&w[k]);
    d_rh[b*II + i] = s / (1.f + expf(-s));
}

__global__ void k_router2(const float* __restrict__ rW2, const float* __restrict__ rb2,
                          float* __restrict__ lb_out) {
    __shared__ float sl[BB][EE];
    __shared__ float sp[BB][EE];
    int tid = threadIdx.x;
    if (tid < BB*EE) {
        int b = tid >> 2, e = tid & 3;
        float s = rb2[e];
        const float* h = d_rh + b*II;
        const float* w = rW2 + e*II;
        for (int k = 0; k < II; ++k) s += h[k]*__ldg(&w[k]);
        sl[b][e] = s;
    }
    __syncthreads();
    if (tid < BB) {
        int b = tid;
        float m = sl[b][0];
        for (int e = 1; e < EE; ++e) m = fmaxf(m, sl[b][e]);
        float p[EE], sum = 0.f;
        for (int e = 0; e < EE; ++e) { p[e] = expf(sl[b][e]-m); sum += p[e]; }
        for (int e = 0; e < EE; ++e) { p[e] /= sum; sp[b][e] = p[e]; }
        int e0 = 0;
        for (int e = 1; e < EE; ++e) if (p[e] > p[e0]) e0 = e;
        int e1 = -1;
        for (int e = 0; e < EE; ++e) { if (e == e0) continue; if (e1 < 0 || p[e] > p[e1]) e1 = e; }
        float z = p[e0] + p[e1];
        d_selE[b][0] = e0; d_selE[b][1] = e1;
        d_selW[b][0] = p[e0]/z; d_selW[b][1] = p[e1]/z;
    }
    __syncthreads();
    if (tid == 0) {
        for (int e = 0; e < EE; ++e) {
            int nn = 0;
            for (int b = 0; b < BB; ++b)
                for (int k = 0; k < 2; ++k)
                    if (d_selE[b][k] == e) { d_rows[e][nn] = b; d_selSlot[b][k] = nn; nn++; }
            d_ne[e] = nn;
            for (int r = nn; r < BB; ++r) d_rows[e][r] = 0;
        }
        float lb = 0.f;
        for (int e = 0; e < EE; ++e) {
            float u = 0.f;
            for (int b = 0; b < BB; ++b) u += sp[b][e];
            u *= (1.f/(float)BB);
            float dv = u - 1.f/(float)EE;
            lb += dv*dv;
        }
        *lb_out = 0.01f * lb * (1.f/(float)EE);
    }
}

// ---------------- xp GEMM (unchanged, proven in R5) ----------------
__global__ void __launch_bounds__(256,2) k_xp(const float* __restrict__ x) {
    __shared__ float As2[8*256];
    __shared__ float Bs [8*128];
    const int e  = blockIdx.z;
    const int r  = blockIdx.y >> 2;
    if (r >= d_ne[e]) return;
    const int t0 = (blockIdx.y & 3)*128;
    const int n0 = blockIdx.x*128;
    const int tid = threadIdx.x;
    const int b = d_rows[e][r];

    const float* Arow = x + ((size_t)b*TT + t0)*II;
    const float* Bmat = d_Wihp + (size_t)e*512*4096 + n0;

    const int i0 = (tid >> 4)*8;
    const int j0 = (tid & 15)*8;

    unsigned long long acc2[8][4];
    #pragma unroll
    for (int i = 0; i < 8; ++i)
        #pragma unroll
        for (int j = 0; j < 4; ++j) acc2[i][j] = 0ull;

    const int sm = tid >> 1, skq = tid & 1;
    const int bk = tid >> 5, bn = (tid & 31)*4;

    for (int kc = 0; kc < 512; kc += 8) {
        {
            float4 v = *(const float4*)&Arow[(size_t)sm*II + kc + skq*4];
            float* dst = &As2[(skq*4)*256 + 2*sm];
            *(float2*)(dst        ) = make_float2(v.x, v.x);
            *(float2*)(dst + 256  ) = make_float2(v.y, v.y);
            *(float2*)(dst + 512  ) = make_float2(v.z, v.z);
            *(float2*)(dst + 768  ) = make_float2(v.w, v.w);
        }
        {
            float4 v = __ldg((const float4*)&Bmat[(size_t)(kc + bk)*4096 + bn]);
            *(float4*)&Bs[bk*128 + bn] = v;
        }
        __syncthreads();
        #pragma unroll
        for (int k = 0; k < 8; ++k) {
            ulonglong2 a01 = *(const ulonglong2*)&As2[k*256 + i0*2];
            ulonglong2 a23 = *(const ulonglong2*)&As2[k*256 + i0*2 + 4];
            ulonglong2 a45 = *(const ulonglong2*)&As2[k*256 + i0*2 + 8];
            ulonglong2 a67 = *(const ulonglong2*)&As2[k*256 + i0*2 + 12];
            ulonglong2 b01 = *(const ulonglong2*)&Bs[k*128 + j0];
            ulonglong2 b23 = *(const ulonglong2*)&Bs[k*128 + j0 + 4];
            ffma2(acc2[0][0], a01.x, b01.x); ffma2(acc2[0][1], a01.x, b01.y);
            ffma2(acc2[0][2], a01.x, b23.x); ffma2(acc2[0][3], a01.x, b23.y);
            ffma2(acc2[1][0], a01.y, b01.x); ffma2(acc2[1][1], a01.y, b01.y);
            ffma2(acc2[1][2], a01.y, b23.x); ffma2(acc2[1][3], a01.y, b23.y);
            ffma2(acc2[2][0], a23.x, b01.x); ffma2(acc2[2][1], a23.x, b01.y);
            ffma2(acc2[2][2], a23.x, b23.x); ffma2(acc2[2][3], a23.x, b23.y);
            ffma2(acc2[3][0], a23.y, b01.x); ffma2(acc2[3][1], a23.y, b01.y);
            ffma2(acc2[3][2], a23.y, b23.x); ffma2(acc2[3][3], a23.y, b23.y);
            ffma2(acc2[4][0], a45.x, b01.x); ffma2(acc2[4][1], a45.x, b01.y);
            ffma2(acc2[4][2], a45.x, b23.x); ffma2(acc2[4][3], a45.x, b23.y);
            ffma2(acc2[5][0], a45.y, b01.x); ffma2(acc2[5][1], a45.y, b01.y);
            ffma2(acc2[5][2], a45.y, b23.x); ffma2(acc2[5][3], a45.y, b23.y);
            ffma2(acc2[6][0], a67.x, b01.x); ffma2(acc2[6][1], a67.x, b01.y);
            ffma2(acc2[6][2], a67.x, b23.x); ffma2(acc2[6][3], a67.x, b23.y);
            ffma2(acc2[7][0], a67.y, b01.x); ffma2(acc2[7][1], a67.y, b01.y);
            ffma2(acc2[7][2], a67.y, b23.x); ffma2(acc2[7][3], a67.y, b23.y);
        }
        __syncthreads();
    }

    float* xpd = d_xp + (((size_t)e*32 + r)*TT)*4096 + n0 + j0;
    #pragma unroll
    for (int i = 0; i < 8; ++i) {
        float2 p0 = *(float2*)&acc2[i][0];
        float2 p1 = *(float2*)&acc2[i][1];
        float2 p2 = *(float2*)&acc2[i][2];
        float2 p3 = *(float2*)&acc2[i][3];
        float* dst = xpd + (size_t)(t0 + i0 + i)*4096;
        *(float4*)(dst    ) = make_float4(p0.x, p0.y, p1.x, p1.y);
        *(float4*)(dst + 4) = make_float4(p2.x, p2.y, p3.x, p3.y);
    }
}

// ---------------- recur compute body: RW interleaved rows (tr, tr+8, ...), 64-k chunk ----------------
template<int RW>
__device__ __forceinline__ void chunk_fma64(const float* __restrict__ As,
                                            const float* __restrict__ wsc,
                                            int tr, int c0, float acc[4][4]) {
    #pragma unroll
    for (int kk = 0; kk < 64; kk += 4) {
        float4 a[RW];
        #pragma unroll
        for (int i = 0; i < RW; ++i)
            a[i] = *(const float4*)&As[(tr + 8*i)*512 + kk];
        #pragma unroll
        for (int u = 0; u < 4; ++u) {
            float4 w = *(const float4*)&wsc[(kk+u)*128 + c0];
            #pragma unroll
            for (int i = 0; i < RW; ++i) {
                float av = (&a[i].x)[u];
                acc[i][0] += av*w.x; acc[i][1] += av*w.y;
                acc[i][2] += av*w.z; acc[i][3] += av*w.w;
            }
        }
    }
}

// ---------------- persistent recurrent kernel: single pass, 8x64k chunks, 16 syncs/step ----------------
// smem floats: As[32*512]=16384 | ws[2][8192]=16384 | gs[32*132]=4224
#define SMEM_RECUR ((16384 + 16384 + 4224)*4)
#define NCH 8

__global__ void __launch_bounds__(256,1) k_recur() {
    extern __shared__ float sm[];
    float* As = sm;                    // 16384
    float* ws = sm + 16384;            // 16384
    float* gs = sm + 32768;            // 4224
    __shared__ int sN;

    const int tid  = threadIdx.x;
    const int bx   = blockIdx.x;
    const int ed   = bx >> 4;
    const int jblk = bx & 15;
    const int e    = ed >> 1;
    const int dback= ed & 1;
    const int tc = tid & 31, tr = tid >> 5;   // tr = warp 0..7
    const int c0 = tc*4;
    const int j0 = jblk*32;

    if (tid == 0) sN = d_ne[e];
    __syncthreads();
    const int n = sN;
    if (n == 0) return;

    // warp tr owns rows tr, tr+8, tr+16, tr+24 (those < n); prefix count:
    int rw = (n - tr + 7) >> 3;
    if (rw < 0) rw = 0;
    if (rw > 4) rw = 4;

    const float4 biasv = *(const float4*)&d_bcat[(ed*16 + jblk)*128 + c0];
    const float* Wblk = d_Whhp + (size_t)(ed*16 + jblk)*65536;
    const float* xpB  = d_xp + (size_t)e*32*TT*4096 + (size_t)dback*2048 + (size_t)jblk*128 + c0;

    const int cr = tid >> 4;           // 0..15: thread owns rows cr and cr+16
    const int cj = (tid & 15)*2;       // col pair
    float creg[2][2] = {{0.f,0.f},{0.f,0.f}};

    unsigned target = 0;
    for (int s = 0; s < TT; ++s) {
        const int t = dback ? (TT-1-s) : s;

        // ---- xp prefetch for this thread's rows ----
        float4 xv[4];
        #pragma unroll
        for (int i = 0; i < 4; ++i) {
            if (i < rw)
                xv[i] = __ldcg((const float4*)(xpB + ((size_t)(tr + 8*i)*TT + t)*4096));
        }

        // ---- stage A = h_prev for rows < n ----
        if (s == 0) {
            for (int idx = tid; idx < n*128; idx += 256)
                ((float4*)As)[idx] = make_float4(0.f,0.f,0.f,0.f);
        } else {
            const float4* hsrc = (const float4*)(d_hstate + (size_t)((s&1)^1)*(NED*BB*HH)
                                                 + (size_t)ed*(BB*HH));
            for (int idx = tid; idx < n*128; idx += 256)
                ((float4*)As)[idx] = __ldcg(hsrc + idx);
        }
        // ---- stage W chunk 0 (64 k) ----
        {
            const float4* src = (const float4*)Wblk;
            float4* dst = (float4*)ws;
            #pragma unroll
            for (int i = 0; i < 8; ++i) dst[tid + i*256] = __ldcg(src + tid + i*256);
        }
        __syncthreads();

        // ---- init accumulators ----
        float acc[4][4];
        #pragma unroll
        for (int i = 0; i < 4; ++i) {
            if (i < rw) {
                acc[i][0] = biasv.x + xv[i].x; acc[i][1] = biasv.y + xv[i].y;
                acc[i][2] = biasv.z + xv[i].z; acc[i][3] = biasv.w + xv[i].w;
            }
        }

        // ---- 8 chunks x 64 k, double buffer ----
        int cur = 0;
        #pragma unroll 1
        for (int cc = 0; cc < NCH; ++cc) {
            float4 pf[8];
            if (cc < NCH-1) {
                const float4* src = (const float4*)(Wblk + (size_t)(cc+1)*8192);
                #pragma unroll
                for (int i = 0; i < 8; ++i) pf[i] = __ldcg(src + tid + i*256);
            }
            {
                const float* wsc = ws + cur*8192;
                const float* Ak  = As + cc*64;
                switch (rw) {
                    case 4: chunk_fma64<4>(Ak, wsc, tr, c0, acc); break;
                    case 3: chunk_fma64<3>(Ak, wsc, tr, c0, acc); break;
                    case 2: chunk_fma64<2>(Ak, wsc, tr, c0, acc); break;
                    case 1: chunk_fma64<1>(Ak, wsc, tr, c0, acc); break;
                    default: break;
                }
            }
            __syncthreads();
            if (cc < NCH-1) {
                float4* dst = (float4*)(ws + (cur^1)*8192);
                #pragma unroll
                for (int i = 0; i < 8; ++i) dst[tid + i*256] = pf[i];
            }
            __syncthreads();
            cur ^= 1;
        }

        // ---- gates to smem ----
        #pragma unroll
        for (int i = 0; i < 4; ++i) {
            if (i < rw)
                *(float4*)&gs[(tr + 8*i)*132 + c0] = make_float4(acc[i][0],acc[i][1],acc[i][2],acc[i][3]);
        }
        __syncthreads();

        // ---- LSTM cell update: rows cr and cr+16 ----
        #pragma unroll
        for (int half = 0; half < 2; ++half) {
            const int row = cr + half*16;
            if (row < n) {
                float hv[2];
                #pragma unroll
                for (int v2 = 0; v2 < 2; ++v2) {
                    int jj = cj + v2;
                    float ig = fsig (gs[row*132 +      jj]);
                    float fg = fsig (gs[row*132 + 32 + jj]);
                    float gg = ftanh(gs[row*132 + 64 + jj]);
                    float og = fsig (gs[row*132 + 96 + jj]);
                    float c = fg*creg[half][v2] + ig*gg;
                    creg[half][v2] = c;
                    hv[v2] = og * ftanh(c);
                }
                float2 h2 = make_float2(hv[0], hv[1]);
                __stcg((float2*)&d_hstate[(size_t)(s&1)*(NED*BB*HH) + (size_t)ed*(BB*HH)
                                          + row*HH + j0 + cj], h2);
                __stcg((float2*)&d_hout[(((size_t)(ed*BB + row))*TT + t)*HH + j0 + cj], h2);
            }
        }
        __syncthreads();

        // ---- per-(e,d) grid barrier (release-arrive + acquire-poll; no extra fence) ----
        target += 16;
        if (tid == 0) {
            asm volatile("red.release.gpu.global.add.u32 [%0], %1;" :: "l"(d_sync + ed*32), "r"(1u) : "memory");
            unsigned v;
            do {
                asm volatile("ld.acquire.gpu.global.u32 %0, [%1];" : "=r"(v) : "l"(d_sync + ed*32) : "memory");
            } while (v < target);
        }
        __syncthreads();
    }
}

// ---------------- combine ----------------
__global__ void k_combine() {
    int idx = blockIdx.x*256 + threadIdx.x;
    int dj4 = idx & 255;
    int t   = (idx >> 8) & 511;
    int b   = idx >> 17;
    int d   = dj4 >> 7;
    int j4  = dj4 & 127;
    float w0 = d_selW[b][0], w1 = d_selW[b][1];
    int e0 = d_selE[b][0],   e1 = d_selE[b][1];
    int s0 = d_selSlot[b][0], s1 = d_selSlot[b][1];
    float4 h0 = *(const float4*)&d_hout[(((size_t)((e0*2+d)*BB + s0))*TT + t)*HH + j4*4];
    float4 h1 = *(const float4*)&d_hout[(((size_t)((e1*2+d)*BB + s1))*TT + t)*HH + j4*4];
    float4 r;
    r.x = w0*h0.x + w1*h1.x; r.y = w0*h0.y + w1*h1.y;
    r.z = w0*h0.z + w1*h1.z; r.w = w0*h0.w + w1*h1.w;
    ((float4*)d_comb)[idx] = r;
}

// ---------------- out GEMM ----------------
__global__ void __launch_bounds__(256) k_outgemm(float* __restrict__ out,
                                                 const float* __restrict__ Wout,
                                                 const float* __restrict__ bout) {
    __shared__ float As[16][68];
    __shared__ float Bs[16][68];
    const int tid = threadIdx.x;
    const int m0 = blockIdx.y*64;
    const int n0 = blockIdx.x*64;
    const int tm = tid >> 4, tn = tid & 15;
    float acc[4][4] = {};
    const int r = tid >> 2, q = tid & 3;
    for (int kc = 0; kc < KKD; kc += 16) {
        float4 a = *(const float4*)&d_comb[(size_t)(m0+r)*KKD + kc + q*4];
        As[q*4+0][r]=a.x; As[q*4+1][r]=a.y; As[q*4+2][r]=a.z; As[q*4+3][r]=a.w;
        float4 bb = __ldg((const float4*)&Wout[(size_t)(n0+r)*KKD + kc + q*4]);
        Bs[q*4+0][r]=bb.x; Bs[q*4+1][r]=bb.y; Bs[q*4+2][r]=bb.z; Bs[q*4+3][r]=bb.w;
        __syncthreads();
        #pragma unroll
        for (int k = 0; k < 16; ++k) {
            float4 av = *(const float4*)&As[k][tm*4];
            float4 bv = *(const float4*)&Bs[k][tn*4];
            acc[0][0]+=av.x*bv.x; acc[0][1]+=av.x*bv.y; acc[0][2]+=av.x*bv.z; acc[0][3]+=av.x*bv.w;
            acc[1][0]+=av.y*bv.x; acc[1][1]+=av.y*bv.y; acc[1][2]+=av.y*bv.z; acc[1][3]+=av.y*bv.w;
            acc[2][0]+=av.z*bv.x; acc[2][1]+=av.z*bv.y; acc[2][2]+=av.z*bv.z; acc[2][3]+=av.z*bv.w;
            acc[3][0]+=av.w*bv.x; acc[3][1]+=av.w*bv.y; acc[3][2]+=av.w*bv.z; acc[3][3]+=av.w*bv.w;
        }
        __syncthreads();
    }
    float4 bv = *(const float4*)&bout[n0 + tn*4];
    #pragma unroll
    for (int i = 0; i < 4; ++i) {
        float4 o;
        o.x = acc[i][0]+bv.x; o.y = acc[i][1]+bv.y; o.z = acc[i][2]+bv.z; o.w = acc[i][3]+bv.w;
        *(float4*)&out[(size_t)(m0+tm*4+i)*OUTD + n0 + tn*4] = o;
    }
}

// ---------------- launch ----------------
extern "C" void kernel_launch(void* const* d_in, const int* in_sizes, int n_in,
                              void* d_out, int out_size) {
    const float* x    = (const float*)d_in[0];
    const float* rW1  = (const float*)d_in[1];
    const float* rb1  = (const float*)d_in[2];
    const float* rW2  = (const float*)d_in[3];
    const float* rb2  = (const float*)d_in[4];
    const float* Wih  = (const float*)d_in[5];
    const float* Whh  = (const float*)d_in[6];
    const float* bih  = (const float*)d_in[7];
    const float* bhh  = (const float*)d_in[8];
    const float* Wout = (const float*)d_in[9];
    const float* bout = (const float*)d_in[10];
    float* out = (float*)d_out;

    float* lbdst;
    if (out_size > NOUT) {
        lbdst = out + NOUT;
    } else {
        cudaGetSymbolAddress((void**)&lbdst, d_lb_dummy);
    }

    static bool attrDone = false;
    if (!attrDone) {
        cudaFuncSetAttribute(k_recur, cudaFuncAttributeMaxDynamicSharedMemorySize, SMEM_RECUR);
        attrDone = true;
    }

    k_zero<<<1, NED*32>>>();
    k_whhp<<<32768, 256>>>(Whh);
    k_wihp<<<32768, 256>>>(Wih);
    k_bcat<<<64, 256>>>(bih, bhh);
    k_mean<<<BB, II>>>(x);
    k_rh<<<BB, II>>>(rW1, rb1);
    k_router2<<<1, 128>>>(rW2, rb2, lbdst);
    k_xp<<<dim3(32, 128, EE), 256>>>(x);
    k_recur<<<NBLK, 256, SMEM_RECUR>>>();
    k_combine<<<16384, 256>>>();
    dim3 g(OUTD/64, (BB*TT)/64);
    k_outgemm<<<g, 256>>>(out, Wout, bout);
}